// round 1
// baseline (speedup 1.0000x reference)
#include <cuda_runtime.h>
#include <cstddef>

#define LLAYERS 6
#define BB 4
#define NN 1024
#define DD 1024
#define HH 16
#define HDIM 64
#define FF 4096
#define MTOK (BB * NN)      /* 4096 */
#define LN_EPS 1e-5f

// ---------------- scratch (no allocations allowed) ----------------
__device__ float g_Q[(size_t)MTOK * DD];
__device__ float g_K[(size_t)MTOK * DD];
__device__ float g_V[(size_t)MTOK * DD];
__device__ float g_T[(size_t)MTOK * DD];
__device__ float g_Y[(size_t)MTOK * DD];
__device__ float g_Hb[(size_t)MTOK * FF];
__device__ float g_S[(size_t)BB * HH * NN * NN];   // 256 MB scores

// =====================================================================
// Main GEMM: C[M,N] = A[M,K] @ W[N,K]^T + bias[N] (+ res[M,N]) (+ relu)
// 128x128 block tile, BK=16, 256 threads, 8x8 per thread.
// M,N multiples of 128; K multiple of 16. All true here.
// =====================================================================
__global__ __launch_bounds__(256) void gemm_nt(
    const float* __restrict__ A, const float* __restrict__ W,
    const float* __restrict__ bias, const float* __restrict__ res,
    float* __restrict__ C, int M, int N, int K, int doRelu)
{
    __shared__ float As[16][128];
    __shared__ float Ws[16][128];

    const int tid = threadIdx.x;
    const int tx = tid & 15;          // 0..15  -> col group
    const int ty = tid >> 4;          // 0..15  -> row group
    const float* Ab = A + (size_t)blockIdx.y * 128 * K;
    const float* Wb = W + (size_t)blockIdx.x * 128 * K;

    float acc[8][8];
#pragma unroll
    for (int i = 0; i < 8; i++)
#pragma unroll
        for (int j = 0; j < 8; j++) acc[i][j] = 0.f;

    for (int k0 = 0; k0 < K; k0 += 16) {
#pragma unroll
        for (int t = 0; t < 2; t++) {
            int idx = tid * 2 + t;            // 0..511
            int row = idx >> 2;               // 0..127
            int kq  = (idx & 3) << 2;         // 0,4,8,12
            float4 a = *(const float4*)(Ab + (size_t)row * K + k0 + kq);
            As[kq + 0][row] = a.x; As[kq + 1][row] = a.y;
            As[kq + 2][row] = a.z; As[kq + 3][row] = a.w;
            float4 w = *(const float4*)(Wb + (size_t)row * K + k0 + kq);
            Ws[kq + 0][row] = w.x; Ws[kq + 1][row] = w.y;
            Ws[kq + 2][row] = w.z; Ws[kq + 3][row] = w.w;
        }
        __syncthreads();
#pragma unroll
        for (int k = 0; k < 16; k++) {
            float af[8], wf[8];
            *(float4*)&af[0] = *(const float4*)&As[k][ty * 8];
            *(float4*)&af[4] = *(const float4*)&As[k][ty * 8 + 4];
            *(float4*)&wf[0] = *(const float4*)&Ws[k][tx * 8];
            *(float4*)&wf[4] = *(const float4*)&Ws[k][tx * 8 + 4];
#pragma unroll
            for (int i = 0; i < 8; i++)
#pragma unroll
                for (int j = 0; j < 8; j++)
                    acc[i][j] = fmaf(af[i], wf[j], acc[i][j]);
        }
        __syncthreads();
    }

#pragma unroll
    for (int i = 0; i < 8; i++) {
        size_t row = (size_t)blockIdx.y * 128 + ty * 8 + i;
#pragma unroll
        for (int j = 0; j < 8; j += 4) {
            int col = blockIdx.x * 128 + tx * 8 + j;
            float4 b4 = *(const float4*)(bias + col);
            float4 v;
            v.x = acc[i][j + 0] + b4.x;
            v.y = acc[i][j + 1] + b4.y;
            v.z = acc[i][j + 2] + b4.z;
            v.w = acc[i][j + 3] + b4.w;
            if (res) {
                float4 r = *(const float4*)(res + row * N + col);
                v.x += r.x; v.y += r.y; v.z += r.z; v.w += r.w;
            }
            if (doRelu) {
                v.x = fmaxf(v.x, 0.f); v.y = fmaxf(v.y, 0.f);
                v.z = fmaxf(v.z, 0.f); v.w = fmaxf(v.w, 0.f);
            }
            *(float4*)(C + row * N + col) = v;
        }
    }
}

// =====================================================================
// Attention scores: S[z,i,j] = scale * dot(Q[b,i,h,:], K[b,j,h,:]) + mask[i,j]
// z = b*H + h. 64x64 tile per block, K-dim = 64, 256 threads, 4x4/thread.
// grid: (N/64 j-tiles, N/64 i-tiles, B*H)
// =====================================================================
__global__ __launch_bounds__(256) void attn_scores(
    const float* __restrict__ Q, const float* __restrict__ Kb,
    const float* __restrict__ mask, float* __restrict__ S, float scale)
{
    __shared__ float As[16][64];
    __shared__ float Ws[16][64];
    const int z = blockIdx.z;
    const int b = z >> 4, h = z & 15;
    const float* Qz = Q + (size_t)b * NN * DD + h * HDIM;
    const float* Kz = Kb + (size_t)b * NN * DD + h * HDIM;
    float* Sz = S + (size_t)z * NN * NN;

    const int tid = threadIdx.x;
    const int tx = tid & 15, ty = tid >> 4;
    const int i0 = blockIdx.y * 64, j0 = blockIdx.x * 64;

    float acc[4][4];
#pragma unroll
    for (int i = 0; i < 4; i++)
#pragma unroll
        for (int j = 0; j < 4; j++) acc[i][j] = 0.f;

    const int row = tid >> 2;          // 0..63
    const int kq  = (tid & 3) << 2;    // 0,4,8,12

    for (int k0 = 0; k0 < HDIM; k0 += 16) {
        float4 a = *(const float4*)(Qz + (size_t)(i0 + row) * DD + k0 + kq);
        As[kq + 0][row] = a.x; As[kq + 1][row] = a.y;
        As[kq + 2][row] = a.z; As[kq + 3][row] = a.w;
        float4 w = *(const float4*)(Kz + (size_t)(j0 + row) * DD + k0 + kq);
        Ws[kq + 0][row] = w.x; Ws[kq + 1][row] = w.y;
        Ws[kq + 2][row] = w.z; Ws[kq + 3][row] = w.w;
        __syncthreads();
#pragma unroll
        for (int k = 0; k < 16; k++) {
            float4 af = *(const float4*)&As[k][ty * 4];
            float4 wf = *(const float4*)&Ws[k][tx * 4];
            acc[0][0] = fmaf(af.x, wf.x, acc[0][0]); acc[0][1] = fmaf(af.x, wf.y, acc[0][1]);
            acc[0][2] = fmaf(af.x, wf.z, acc[0][2]); acc[0][3] = fmaf(af.x, wf.w, acc[0][3]);
            acc[1][0] = fmaf(af.y, wf.x, acc[1][0]); acc[1][1] = fmaf(af.y, wf.y, acc[1][1]);
            acc[1][2] = fmaf(af.y, wf.z, acc[1][2]); acc[1][3] = fmaf(af.y, wf.w, acc[1][3]);
            acc[2][0] = fmaf(af.z, wf.x, acc[2][0]); acc[2][1] = fmaf(af.z, wf.y, acc[2][1]);
            acc[2][2] = fmaf(af.z, wf.z, acc[2][2]); acc[2][3] = fmaf(af.z, wf.w, acc[2][3]);
            acc[3][0] = fmaf(af.w, wf.x, acc[3][0]); acc[3][1] = fmaf(af.w, wf.y, acc[3][1]);
            acc[3][2] = fmaf(af.w, wf.z, acc[3][2]); acc[3][3] = fmaf(af.w, wf.w, acc[3][3]);
        }
        __syncthreads();
    }

#pragma unroll
    for (int i = 0; i < 4; i++) {
        size_t ri = (size_t)(i0 + ty * 4 + i);
        int cj = j0 + tx * 4;
        float4 mk = *(const float4*)(mask + ri * NN + cj);
        float4 v;
        v.x = acc[i][0] * scale + mk.x;
        v.y = acc[i][1] * scale + mk.y;
        v.z = acc[i][2] * scale + mk.z;
        v.w = acc[i][3] * scale + mk.w;
        *(float4*)(Sz + ri * NN + cj) = v;
    }
}

// =====================================================================
// Row softmax over last dim (1024), one block per row.
// =====================================================================
__global__ __launch_bounds__(256) void softmax_row(float* __restrict__ S)
{
    __shared__ float red[256];
    const size_t base = (size_t)blockIdx.x * NN;
    const int tid = threadIdx.x;
    float4 v = *(const float4*)(S + base + tid * 4);

    float m = fmaxf(fmaxf(v.x, v.y), fmaxf(v.z, v.w));
    red[tid] = m; __syncthreads();
    for (int s = 128; s > 0; s >>= 1) {
        if (tid < s) red[tid] = fmaxf(red[tid], red[tid + s]);
        __syncthreads();
    }
    float rmax = red[0]; __syncthreads();

    v.x = __expf(v.x - rmax); v.y = __expf(v.y - rmax);
    v.z = __expf(v.z - rmax); v.w = __expf(v.w - rmax);
    red[tid] = v.x + v.y + v.z + v.w; __syncthreads();
    for (int s = 128; s > 0; s >>= 1) {
        if (tid < s) red[tid] += red[tid + s];
        __syncthreads();
    }
    float inv = 1.f / red[0];
    v.x *= inv; v.y *= inv; v.z *= inv; v.w *= inv;
    *(float4*)(S + base + tid * 4) = v;
}

// =====================================================================
// O = P @ V per (b,h): T[b,i,h*64+d] = sum_j P[z,i,j] * V[b,j,h*64+d]
// 64x64 i-tile, full 64 cols, K=N=1024. grid: (1, N/64, B*H)
// =====================================================================
__global__ __launch_bounds__(256) void attn_av(
    const float* __restrict__ P, const float* __restrict__ V,
    float* __restrict__ T)
{
    __shared__ float As[16][64];
    __shared__ float Ws[16][64];
    const int z = blockIdx.z;
    const int b = z >> 4, h = z & 15;
    const float* Pz = P + (size_t)z * NN * NN;
    const float* Vz = V + (size_t)b * NN * DD + h * HDIM;
    float* Tz = T + (size_t)b * NN * DD + h * HDIM;

    const int tid = threadIdx.x;
    const int tx = tid & 15, ty = tid >> 4;
    const int i0 = blockIdx.y * 64;

    float acc[4][4];
#pragma unroll
    for (int i = 0; i < 4; i++)
#pragma unroll
        for (int j = 0; j < 4; j++) acc[i][j] = 0.f;

    const int arow = tid >> 2, akq = (tid & 3) << 2;   // A load
    const int krow = tid >> 4, nq = (tid & 15) << 2;   // B load

    for (int k0 = 0; k0 < NN; k0 += 16) {
        float4 a = *(const float4*)(Pz + (size_t)(i0 + arow) * NN + k0 + akq);
        As[akq + 0][arow] = a.x; As[akq + 1][arow] = a.y;
        As[akq + 2][arow] = a.z; As[akq + 3][arow] = a.w;
        *(float4*)&Ws[krow][nq] =
            *(const float4*)(Vz + (size_t)(k0 + krow) * DD + nq);
        __syncthreads();
#pragma unroll
        for (int k = 0; k < 16; k++) {
            float4 af = *(const float4*)&As[k][ty * 4];
            float4 wf = *(const float4*)&Ws[k][tx * 4];
            acc[0][0] = fmaf(af.x, wf.x, acc[0][0]); acc[0][1] = fmaf(af.x, wf.y, acc[0][1]);
            acc[0][2] = fmaf(af.x, wf.z, acc[0][2]); acc[0][3] = fmaf(af.x, wf.w, acc[0][3]);
            acc[1][0] = fmaf(af.y, wf.x, acc[1][0]); acc[1][1] = fmaf(af.y, wf.y, acc[1][1]);
            acc[1][2] = fmaf(af.y, wf.z, acc[1][2]); acc[1][3] = fmaf(af.y, wf.w, acc[1][3]);
            acc[2][0] = fmaf(af.z, wf.x, acc[2][0]); acc[2][1] = fmaf(af.z, wf.y, acc[2][1]);
            acc[2][2] = fmaf(af.z, wf.z, acc[2][2]); acc[2][3] = fmaf(af.z, wf.w, acc[2][3]);
            acc[3][0] = fmaf(af.w, wf.x, acc[3][0]); acc[3][1] = fmaf(af.w, wf.y, acc[3][1]);
            acc[3][2] = fmaf(af.w, wf.z, acc[3][2]); acc[3][3] = fmaf(af.w, wf.w, acc[3][3]);
        }
        __syncthreads();
    }

#pragma unroll
    for (int i = 0; i < 4; i++) {
        size_t ri = (size_t)(i0 + ty * 4 + i);
        float4 v; v.x = acc[i][0]; v.y = acc[i][1]; v.z = acc[i][2]; v.w = acc[i][3];
        *(float4*)(Tz + ri * DD + tx * 4) = v;
    }
}

// =====================================================================
// LayerNorm over last dim (1024). One block per row. In-place safe.
// =====================================================================
__global__ __launch_bounds__(256) void layernorm_row(
    const float* __restrict__ X, const float* __restrict__ g,
    const float* __restrict__ bta, float* __restrict__ Y)
{
    __shared__ float red[256];
    const size_t base = (size_t)blockIdx.x * DD;
    const int tid = threadIdx.x;
    float4 v = *(const float4*)(X + base + tid * 4);

    red[tid] = v.x + v.y + v.z + v.w; __syncthreads();
    for (int s = 128; s > 0; s >>= 1) {
        if (tid < s) red[tid] += red[tid + s];
        __syncthreads();
    }
    float mean = red[0] * (1.f / DD); __syncthreads();

    float dx = v.x - mean, dy = v.y - mean, dz = v.z - mean, dw = v.w - mean;
    red[tid] = dx * dx + dy * dy + dz * dz + dw * dw; __syncthreads();
    for (int s = 128; s > 0; s >>= 1) {
        if (tid < s) red[tid] += red[tid + s];
        __syncthreads();
    }
    float inv = rsqrtf(red[0] * (1.f / DD) + LN_EPS);

    float4 gg = *(const float4*)(g + tid * 4);
    float4 bb = *(const float4*)(bta + tid * 4);
    float4 o;
    o.x = dx * inv * gg.x + bb.x;
    o.y = dy * inv * gg.y + bb.y;
    o.z = dz * inv * gg.z + bb.z;
    o.w = dw * inv * gg.w + bb.w;
    *(float4*)(Y + base + tid * 4) = o;
}

// =====================================================================
// Host orchestration
// =====================================================================
static void run_attention(const float* Q, const float* Kb, const float* V,
                          float* S, float* T, const float* mask)
{
    dim3 blk(256);
    attn_scores<<<dim3(NN / 64, NN / 64, BB * HH), blk>>>(Q, Kb, mask, S, 0.125f);
    softmax_row<<<BB * HH * NN, blk>>>(S);
    attn_av<<<dim3(1, NN / 64, BB * HH), blk>>>(S, V, T);
}

extern "C" void kernel_launch(void* const* d_in, const int* in_sizes, int n_in,
                              void* d_out, int out_size)
{
    const float* feats    = (const float*)d_in[0];
    const float* enc      = (const float*)d_in[1];
    const float* trg_mask = (const float*)d_in[2];
    const float* src_mask = (const float*)d_in[3];
    const float* wq1 = (const float*)d_in[4];  const float* bq1 = (const float*)d_in[5];
    const float* wk1 = (const float*)d_in[6];  const float* bk1 = (const float*)d_in[7];
    const float* wv1 = (const float*)d_in[8];  const float* bv1 = (const float*)d_in[9];
    const float* wo1 = (const float*)d_in[10]; const float* bo1 = (const float*)d_in[11];
    const float* wq2 = (const float*)d_in[12]; const float* bq2 = (const float*)d_in[13];
    const float* wk2 = (const float*)d_in[14]; const float* bk2 = (const float*)d_in[15];
    const float* wv2 = (const float*)d_in[16]; const float* bv2 = (const float*)d_in[17];
    const float* wo2 = (const float*)d_in[18]; const float* bo2 = (const float*)d_in[19];
    const float* wf1 = (const float*)d_in[20]; const float* bf1 = (const float*)d_in[21];
    const float* wf2 = (const float*)d_in[22]; const float* bf2 = (const float*)d_in[23];
    const float* g1  = (const float*)d_in[24]; const float* be1 = (const float*)d_in[25];
    const float* g2  = (const float*)d_in[26]; const float* be2 = (const float*)d_in[27];
    const float* g3  = (const float*)d_in[28]; const float* be3 = (const float*)d_in[29];
    float* out = (float*)d_out;

    float *Q, *K, *V, *T, *Y, *Hb, *S;
    cudaGetSymbolAddress((void**)&Q,  g_Q);
    cudaGetSymbolAddress((void**)&K,  g_K);
    cudaGetSymbolAddress((void**)&V,  g_V);
    cudaGetSymbolAddress((void**)&T,  g_T);
    cudaGetSymbolAddress((void**)&Y,  g_Y);
    cudaGetSymbolAddress((void**)&Hb, g_Hb);
    cudaGetSymbolAddress((void**)&S,  g_S);

    dim3 blk(256);
    dim3 gD(DD / 128, MTOK / 128);   // 4096 x 1024 outputs
    dim3 gF(FF / 128, MTOK / 128);   // 4096 x 4096 outputs

    const float* X = enc;            // decoder state entering layer l
    for (int l = 0; l < LLAYERS; l++) {
        const float* feat = feats + (size_t)l * MTOK * DD;
        const size_t wOff = (size_t)l * DD * DD;
        const size_t vOff = (size_t)l * DD;

        // ---- attn1: cross-attention (q from feat, k/v from enc, src_mask) ----
        gemm_nt<<<gD, blk>>>(feat, wq1 + wOff, bq1 + vOff, nullptr, Q, MTOK, DD, DD, 0);
        gemm_nt<<<gD, blk>>>(enc,  wk1 + wOff, bk1 + vOff, nullptr, K, MTOK, DD, DD, 0);
        gemm_nt<<<gD, blk>>>(enc,  wv1 + wOff, bv1 + vOff, nullptr, V, MTOK, DD, DD, 0);
        run_attention(Q, K, V, S, T, src_mask);
        gemm_nt<<<gD, blk>>>(T, wo1 + wOff, bo1 + vOff, feat, Y, MTOK, DD, DD, 0);
        layernorm_row<<<MTOK, blk>>>(Y, g1 + vOff, be1 + vOff, Y);

        // ---- attn2: attention to previous decoder output (trg_mask) ----
        gemm_nt<<<gD, blk>>>(Y, wq2 + wOff, bq2 + vOff, nullptr, Q, MTOK, DD, DD, 0);
        gemm_nt<<<gD, blk>>>(X, wk2 + wOff, bk2 + vOff, nullptr, K, MTOK, DD, DD, 0);
        gemm_nt<<<gD, blk>>>(X, wv2 + wOff, bv2 + vOff, nullptr, V, MTOK, DD, DD, 0);
        run_attention(Q, K, V, S, T, trg_mask);
        gemm_nt<<<gD, blk>>>(T, wo2 + wOff, bo2 + vOff, Y, Y, MTOK, DD, DD, 0);
        layernorm_row<<<MTOK, blk>>>(Y, g2 + vOff, be2 + vOff, Y);

        // ---- FFN ----
        gemm_nt<<<gF, blk>>>(Y, wf1 + (size_t)l * FF * DD, bf1 + (size_t)l * FF,
                             nullptr, Hb, MTOK, FF, DD, 1);
        gemm_nt<<<gD, blk>>>(Hb, wf2 + (size_t)l * DD * FF, bf2 + vOff, Y, Y,
                             MTOK, DD, FF, 0);
        float* outl = out + (size_t)l * MTOK * DD;
        layernorm_row<<<MTOK, blk>>>(Y, g3 + vOff, be3 + vOff, outl);

        X = outl;   // next layer reads decoder state from the output slab
    }
    (void)in_sizes; (void)n_in; (void)out_size;
}

// round 2
// speedup vs baseline: 1.7678x; 1.7678x over previous
#include <cuda_runtime.h>
#include <mma.h>
#include <cstddef>

using namespace nvcuda;

#define LLAYERS 6
#define BB 4
#define NN 1024
#define DD 1024
#define HH 16
#define HDIM 64
#define FF 4096
#define MTOK (BB * NN)      /* 4096 */
#define LN_EPS 1e-5f

// ---------------- scratch (no allocations allowed) ----------------
__device__ float g_Q[(size_t)MTOK * DD];
__device__ float g_K[(size_t)MTOK * DD];
__device__ float g_V[(size_t)MTOK * DD];
__device__ float g_T[(size_t)MTOK * DD];
__device__ float g_Y[(size_t)MTOK * DD];
__device__ float g_Hb[(size_t)MTOK * FF];
__device__ float g_S[(size_t)BB * HH * NN * NN];   // 256 MB scores

// =====================================================================
// TF32 tensor-core GEMM: C[M,N] = A[M,K] @ W[N,K]^T + bias (+res) (+relu)
// 128x128 block tile, BK=16, 256 threads = 8 warps, warp tile 64x32.
// wmma m16n16k8 tf32. M,N mult of 128; K mult of 16.
// =====================================================================
#define GBK 16
#define GST (GBK + 8)   /* 24 floats: row stride, 96B (16B-aligned) */

__global__ __launch_bounds__(256) void gemm_nt_tc(
    const float* __restrict__ A, const float* __restrict__ W,
    const float* __restrict__ bias, const float* __restrict__ res,
    float* __restrict__ C, int M, int N, int K, int doRelu)
{
    __shared__ float As[128][GST];
    __shared__ float Ws[128][GST];
    __shared__ float stage[8][16 * 16];

    const int tid  = threadIdx.x;
    const int warp = tid >> 5;
    const int lane = tid & 31;
    const int wm   = warp >> 2;   // 0..1 -> m offset wm*64
    const int wn   = warp & 3;    // 0..3 -> n offset wn*32

    const float* Ab = A + (size_t)blockIdx.y * 128 * K;
    const float* Wb = W + (size_t)blockIdx.x * 128 * K;

    wmma::fragment<wmma::accumulator, 16, 16, 8, float> acc[4][2];
#pragma unroll
    for (int i = 0; i < 4; i++)
#pragma unroll
        for (int j = 0; j < 2; j++) wmma::fill_fragment(acc[i][j], 0.f);

    for (int k0 = 0; k0 < K; k0 += GBK) {
        // each tile is 128x16 f32 = 512 float4; 256 threads -> 2 each
#pragma unroll
        for (int t = 0; t < 2; t++) {
            int idx = tid + t * 256;
            int row = idx >> 2;
            int cq  = (idx & 3) << 2;
            float4 a = *(const float4*)(Ab + (size_t)row * K + k0 + cq);
            As[row][cq + 0] = wmma::__float_to_tf32(a.x);
            As[row][cq + 1] = wmma::__float_to_tf32(a.y);
            As[row][cq + 2] = wmma::__float_to_tf32(a.z);
            As[row][cq + 3] = wmma::__float_to_tf32(a.w);
            float4 w = *(const float4*)(Wb + (size_t)row * K + k0 + cq);
            Ws[row][cq + 0] = wmma::__float_to_tf32(w.x);
            Ws[row][cq + 1] = wmma::__float_to_tf32(w.y);
            Ws[row][cq + 2] = wmma::__float_to_tf32(w.z);
            Ws[row][cq + 3] = wmma::__float_to_tf32(w.w);
        }
        __syncthreads();
#pragma unroll
        for (int kk = 0; kk < GBK; kk += 8) {
            wmma::fragment<wmma::matrix_a, 16, 16, 8, wmma::precision::tf32,
                           wmma::row_major> af[4];
#pragma unroll
            for (int i = 0; i < 4; i++)
                wmma::load_matrix_sync(af[i], &As[wm * 64 + i * 16][kk], GST);
            wmma::fragment<wmma::matrix_b, 16, 16, 8, wmma::precision::tf32,
                           wmma::col_major> bf[2];
#pragma unroll
            for (int j = 0; j < 2; j++)
                wmma::load_matrix_sync(bf[j], &Ws[wn * 32 + j * 16][kk], GST);
#pragma unroll
            for (int i = 0; i < 4; i++)
#pragma unroll
                for (int j = 0; j < 2; j++)
                    wmma::mma_sync(acc[i][j], af[i], bf[j], acc[i][j]);
        }
        __syncthreads();
    }

    // epilogue: per-warp 16x16 staging, fused bias/res/relu
#pragma unroll
    for (int i = 0; i < 4; i++) {
#pragma unroll
        for (int j = 0; j < 2; j++) {
            wmma::store_matrix_sync(stage[warp], acc[i][j], 16, wmma::mem_row_major);
            __syncwarp();
            int r0 = blockIdx.y * 128 + wm * 64 + i * 16;
            int c0 = blockIdx.x * 128 + wn * 32 + j * 16;
#pragma unroll
            for (int e = 0; e < 2; e++) {
                int idx = lane + e * 32;       // 0..63 float4 units
                int rr  = idx >> 2;
                int cc  = (idx & 3) << 2;
                float4 v  = *(float4*)&stage[warp][rr * 16 + cc];
                float4 b4 = *(const float4*)(bias + c0 + cc);
                v.x += b4.x; v.y += b4.y; v.z += b4.z; v.w += b4.w;
                size_t row = (size_t)(r0 + rr);
                if (res) {
                    float4 r = *(const float4*)(res + row * N + c0 + cc);
                    v.x += r.x; v.y += r.y; v.z += r.z; v.w += r.w;
                }
                if (doRelu) {
                    v.x = fmaxf(v.x, 0.f); v.y = fmaxf(v.y, 0.f);
                    v.z = fmaxf(v.z, 0.f); v.w = fmaxf(v.w, 0.f);
                }
                *(float4*)(C + row * N + c0 + cc) = v;
            }
            __syncwarp();
        }
    }
}

// =====================================================================
// Attention scores (TF32 TC): S[z,i,j] = scale * dot(Q[b,i,h,:],K[b,j,h,:])
// (mask folded into softmax). 64x64 tile, 128 threads = 4 warps (2x2),
// warp tile 32x32. HD=64 fully resident in smem.
// grid: (N/64 j, N/64 i, B*H)
// =====================================================================
#define QST 72

__global__ __launch_bounds__(128) void attn_scores_tc(
    const float* __restrict__ Q, const float* __restrict__ Kb,
    float* __restrict__ S, float scale)
{
    __shared__ float Qs[64][QST];
    __shared__ float Ks[64][QST];
    const int z = blockIdx.z;
    const int b = z >> 4, h = z & 15;
    const float* Qz = Q + (size_t)b * NN * DD + h * HDIM;
    const float* Kz = Kb + (size_t)b * NN * DD + h * HDIM;
    float* Sz = S + (size_t)z * NN * NN;

    const int tid = threadIdx.x;
    const int warp = tid >> 5;
    const int wm = warp >> 1, wn = warp & 1;
    const int i0 = blockIdx.y * 64, j0 = blockIdx.x * 64;

    // load 64x64 Q and K tiles: 1024 float4 each; 128 threads -> 8 each
#pragma unroll
    for (int t = 0; t < 8; t++) {
        int idx = tid + t * 128;
        int row = idx >> 4;
        int cq  = (idx & 15) << 2;
        float4 a = *(const float4*)(Qz + (size_t)(i0 + row) * DD + cq);
        Qs[row][cq + 0] = wmma::__float_to_tf32(a.x);
        Qs[row][cq + 1] = wmma::__float_to_tf32(a.y);
        Qs[row][cq + 2] = wmma::__float_to_tf32(a.z);
        Qs[row][cq + 3] = wmma::__float_to_tf32(a.w);
        float4 k = *(const float4*)(Kz + (size_t)(j0 + row) * DD + cq);
        Ks[row][cq + 0] = wmma::__float_to_tf32(k.x);
        Ks[row][cq + 1] = wmma::__float_to_tf32(k.y);
        Ks[row][cq + 2] = wmma::__float_to_tf32(k.z);
        Ks[row][cq + 3] = wmma::__float_to_tf32(k.w);
    }
    __syncthreads();

    wmma::fragment<wmma::accumulator, 16, 16, 8, float> acc[2][2];
#pragma unroll
    for (int i = 0; i < 2; i++)
#pragma unroll
        for (int j = 0; j < 2; j++) wmma::fill_fragment(acc[i][j], 0.f);

#pragma unroll
    for (int kk = 0; kk < HDIM; kk += 8) {
        wmma::fragment<wmma::matrix_a, 16, 16, 8, wmma::precision::tf32,
                       wmma::row_major> af[2];
        wmma::fragment<wmma::matrix_b, 16, 16, 8, wmma::precision::tf32,
                       wmma::col_major> bf[2];
#pragma unroll
        for (int i = 0; i < 2; i++)
            wmma::load_matrix_sync(af[i], &Qs[wm * 32 + i * 16][kk], QST);
#pragma unroll
        for (int j = 0; j < 2; j++)
            wmma::load_matrix_sync(bf[j], &Ks[wn * 32 + j * 16][kk], QST);
#pragma unroll
        for (int i = 0; i < 2; i++)
#pragma unroll
            for (int j = 0; j < 2; j++)
                wmma::mma_sync(acc[i][j], af[i], bf[j], acc[i][j]);
    }

#pragma unroll
    for (int i = 0; i < 2; i++)
#pragma unroll
        for (int j = 0; j < 2; j++) {
#pragma unroll
            for (int e = 0; e < acc[i][j].num_elements; e++)
                acc[i][j].x[e] *= scale;
            size_t ri = (size_t)(i0 + wm * 32 + i * 16);
            int cj = j0 + wn * 32 + j * 16;
            wmma::store_matrix_sync(Sz + ri * NN + cj, acc[i][j], NN,
                                    wmma::mem_row_major);
        }
}

// =====================================================================
// Row softmax over last dim (1024), mask folded in. One block per row.
// =====================================================================
__global__ __launch_bounds__(256) void softmax_row(
    float* __restrict__ S, const float* __restrict__ mask)
{
    __shared__ float red[256];
    const size_t base = (size_t)blockIdx.x * NN;
    const int i = blockIdx.x & (NN - 1);
    const int tid = threadIdx.x;
    float4 v = *(const float4*)(S + base + tid * 4);
    float4 mk = *(const float4*)(mask + (size_t)i * NN + tid * 4);
    v.x += mk.x; v.y += mk.y; v.z += mk.z; v.w += mk.w;

    float m = fmaxf(fmaxf(v.x, v.y), fmaxf(v.z, v.w));
    red[tid] = m; __syncthreads();
    for (int s = 128; s > 0; s >>= 1) {
        if (tid < s) red[tid] = fmaxf(red[tid], red[tid + s]);
        __syncthreads();
    }
    float rmax = red[0]; __syncthreads();

    v.x = __expf(v.x - rmax); v.y = __expf(v.y - rmax);
    v.z = __expf(v.z - rmax); v.w = __expf(v.w - rmax);
    red[tid] = v.x + v.y + v.z + v.w; __syncthreads();
    for (int s = 128; s > 0; s >>= 1) {
        if (tid < s) red[tid] += red[tid + s];
        __syncthreads();
    }
    float inv = 1.f / red[0];
    v.x *= inv; v.y *= inv; v.z *= inv; v.w *= inv;
    *(float4*)(S + base + tid * 4) = v;
}

// =====================================================================
// O = P @ V per (b,h) with TF32 TC. 64(i) x 64(d) tile, K=N=1024.
// 128 threads = 4 warps (2x2), warp tile 32x32. grid: (N/64, B*H)
// =====================================================================
#define PST 24
#define VST 72

__global__ __launch_bounds__(128) void attn_av_tc(
    const float* __restrict__ P, const float* __restrict__ V,
    float* __restrict__ T)
{
    __shared__ float Ps[64][PST];
    __shared__ float Vs[16][VST];
    const int z = blockIdx.y;
    const int b = z >> 4, h = z & 15;
    const float* Pz = P + (size_t)z * NN * NN;
    const float* Vz = V + (size_t)b * NN * DD + h * HDIM;
    float* Tz = T + (size_t)b * NN * DD + h * HDIM;

    const int tid = threadIdx.x;
    const int warp = tid >> 5;
    const int wm = warp >> 1, wn = warp & 1;
    const int i0 = blockIdx.x * 64;

    wmma::fragment<wmma::accumulator, 16, 16, 8, float> acc[2][2];
#pragma unroll
    for (int i = 0; i < 2; i++)
#pragma unroll
        for (int j = 0; j < 2; j++) wmma::fill_fragment(acc[i][j], 0.f);

    for (int k0 = 0; k0 < NN; k0 += 16) {
        // P tile 64x16 = 256 float4; 128 threads -> 2 each
#pragma unroll
        for (int t = 0; t < 2; t++) {
            int idx = tid + t * 128;
            int row = idx >> 2;
            int cq  = (idx & 3) << 2;
            float4 a = *(const float4*)(Pz + (size_t)(i0 + row) * NN + k0 + cq);
            Ps[row][cq + 0] = wmma::__float_to_tf32(a.x);
            Ps[row][cq + 1] = wmma::__float_to_tf32(a.y);
            Ps[row][cq + 2] = wmma::__float_to_tf32(a.z);
            Ps[row][cq + 3] = wmma::__float_to_tf32(a.w);
        }
        // V tile 16x64 = 256 float4
#pragma unroll
        for (int t = 0; t < 2; t++) {
            int idx = tid + t * 128;
            int row = idx >> 4;
            int cq  = (idx & 15) << 2;
            float4 w = *(const float4*)(Vz + (size_t)(k0 + row) * DD + cq);
            Vs[row][cq + 0] = wmma::__float_to_tf32(w.x);
            Vs[row][cq + 1] = wmma::__float_to_tf32(w.y);
            Vs[row][cq + 2] = wmma::__float_to_tf32(w.z);
            Vs[row][cq + 3] = wmma::__float_to_tf32(w.w);
        }
        __syncthreads();
#pragma unroll
        for (int kk = 0; kk < 16; kk += 8) {
            wmma::fragment<wmma::matrix_a, 16, 16, 8, wmma::precision::tf32,
                           wmma::row_major> af[2];
            wmma::fragment<wmma::matrix_b, 16, 16, 8, wmma::precision::tf32,
                           wmma::row_major> bf[2];
#pragma unroll
            for (int i = 0; i < 2; i++)
                wmma::load_matrix_sync(af[i], &Ps[wm * 32 + i * 16][kk], PST);
#pragma unroll
            for (int j = 0; j < 2; j++)
                wmma::load_matrix_sync(bf[j], &Vs[kk][wn * 32 + j * 16], VST);
#pragma unroll
            for (int i = 0; i < 2; i++)
#pragma unroll
                for (int j = 0; j < 2; j++)
                    wmma::mma_sync(acc[i][j], af[i], bf[j], acc[i][j]);
        }
        __syncthreads();
    }

#pragma unroll
    for (int i = 0; i < 2; i++)
#pragma unroll
        for (int j = 0; j < 2; j++) {
            size_t ri = (size_t)(i0 + wm * 32 + i * 16);
            int cj = wn * 32 + j * 16;
            wmma::store_matrix_sync(Tz + ri * DD + cj, acc[i][j], DD,
                                    wmma::mem_row_major);
        }
}

// =====================================================================
// LayerNorm over last dim (1024). One block per row. In-place safe.
// =====================================================================
__global__ __launch_bounds__(256) void layernorm_row(
    const float* __restrict__ X, const float* __restrict__ g,
    const float* __restrict__ bta, float* __restrict__ Y)
{
    __shared__ float red[256];
    const size_t base = (size_t)blockIdx.x * DD;
    const int tid = threadIdx.x;
    float4 v = *(const float4*)(X + base + tid * 4);

    red[tid] = v.x + v.y + v.z + v.w; __syncthreads();
    for (int s = 128; s > 0; s >>= 1) {
        if (tid < s) red[tid] += red[tid + s];
        __syncthreads();
    }
    float mean = red[0] * (1.f / DD); __syncthreads();

    float dx = v.x - mean, dy = v.y - mean, dz = v.z - mean, dw = v.w - mean;
    red[tid] = dx * dx + dy * dy + dz * dz + dw * dw; __syncthreads();
    for (int s = 128; s > 0; s >>= 1) {
        if (tid < s) red[tid] += red[tid + s];
        __syncthreads();
    }
    float inv = rsqrtf(red[0] * (1.f / DD) + LN_EPS);

    float4 gg = *(const float4*)(g + tid * 4);
    float4 bb = *(const float4*)(bta + tid * 4);
    float4 o;
    o.x = dx * inv * gg.x + bb.x;
    o.y = dy * inv * gg.y + bb.y;
    o.z = dz * inv * gg.z + bb.z;
    o.w = dw * inv * gg.w + bb.w;
    *(float4*)(Y + base + tid * 4) = o;
}

// =====================================================================
// Host orchestration
// =====================================================================
static void run_attention(const float* Q, const float* Kb, const float* V,
                          float* S, float* T, const float* mask)
{
    attn_scores_tc<<<dim3(NN / 64, NN / 64, BB * HH), 128>>>(Q, Kb, S, 0.125f);
    softmax_row<<<BB * HH * NN, 256>>>(S, mask);
    attn_av_tc<<<dim3(NN / 64, BB * HH), 128>>>(S, V, T);
}

extern "C" void kernel_launch(void* const* d_in, const int* in_sizes, int n_in,
                              void* d_out, int out_size)
{
    const float* feats    = (const float*)d_in[0];
    const float* enc      = (const float*)d_in[1];
    const float* trg_mask = (const float*)d_in[2];
    const float* src_mask = (const float*)d_in[3];
    const float* wq1 = (const float*)d_in[4];  const float* bq1 = (const float*)d_in[5];
    const float* wk1 = (const float*)d_in[6];  const float* bk1 = (const float*)d_in[7];
    const float* wv1 = (const float*)d_in[8];  const float* bv1 = (const float*)d_in[9];
    const float* wo1 = (const float*)d_in[10]; const float* bo1 = (const float*)d_in[11];
    const float* wq2 = (const float*)d_in[12]; const float* bq2 = (const float*)d_in[13];
    const float* wk2 = (const float*)d_in[14]; const float* bk2 = (const float*)d_in[15];
    const float* wv2 = (const float*)d_in[16]; const float* bv2 = (const float*)d_in[17];
    const float* wo2 = (const float*)d_in[18]; const float* bo2 = (const float*)d_in[19];
    const float* wf1 = (const float*)d_in[20]; const float* bf1 = (const float*)d_in[21];
    const float* wf2 = (const float*)d_in[22]; const float* bf2 = (const float*)d_in[23];
    const float* g1  = (const float*)d_in[24]; const float* be1 = (const float*)d_in[25];
    const float* g2  = (const float*)d_in[26]; const float* be2 = (const float*)d_in[27];
    const float* g3  = (const float*)d_in[28]; const float* be3 = (const float*)d_in[29];
    float* out = (float*)d_out;

    float *Q, *K, *V, *T, *Y, *Hb, *S;
    cudaGetSymbolAddress((void**)&Q,  g_Q);
    cudaGetSymbolAddress((void**)&K,  g_K);
    cudaGetSymbolAddress((void**)&V,  g_V);
    cudaGetSymbolAddress((void**)&T,  g_T);
    cudaGetSymbolAddress((void**)&Y,  g_Y);
    cudaGetSymbolAddress((void**)&Hb, g_Hb);
    cudaGetSymbolAddress((void**)&S,  g_S);

    dim3 blk(256);
    dim3 gD(DD / 128, MTOK / 128);   // 4096 x 1024 outputs
    dim3 gF(FF / 128, MTOK / 128);   // 4096 x 4096 outputs

    const float* X = enc;            // decoder state entering layer l
    for (int l = 0; l < LLAYERS; l++) {
        const float* feat = feats + (size_t)l * MTOK * DD;
        const size_t wOff = (size_t)l * DD * DD;
        const size_t vOff = (size_t)l * DD;

        // ---- attn1: cross-attention (q from feat, k/v from enc, src_mask) ----
        gemm_nt_tc<<<gD, blk>>>(feat, wq1 + wOff, bq1 + vOff, nullptr, Q, MTOK, DD, DD, 0);
        gemm_nt_tc<<<gD, blk>>>(enc,  wk1 + wOff, bk1 + vOff, nullptr, K, MTOK, DD, DD, 0);
        gemm_nt_tc<<<gD, blk>>>(enc,  wv1 + wOff, bv1 + vOff, nullptr, V, MTOK, DD, DD, 0);
        run_attention(Q, K, V, S, T, src_mask);
        gemm_nt_tc<<<gD, blk>>>(T, wo1 + wOff, bo1 + vOff, feat, Y, MTOK, DD, DD, 0);
        layernorm_row<<<MTOK, blk>>>(Y, g1 + vOff, be1 + vOff, Y);

        // ---- attn2: attention to previous decoder output (trg_mask) ----
        gemm_nt_tc<<<gD, blk>>>(Y, wq2 + wOff, bq2 + vOff, nullptr, Q, MTOK, DD, DD, 0);
        gemm_nt_tc<<<gD, blk>>>(X, wk2 + wOff, bk2 + vOff, nullptr, K, MTOK, DD, DD, 0);
        gemm_nt_tc<<<gD, blk>>>(X, wv2 + wOff, bv2 + vOff, nullptr, V, MTOK, DD, DD, 0);
        run_attention(Q, K, V, S, T, trg_mask);
        gemm_nt_tc<<<gD, blk>>>(T, wo2 + wOff, bo2 + vOff, Y, Y, MTOK, DD, DD, 0);
        layernorm_row<<<MTOK, blk>>>(Y, g2 + vOff, be2 + vOff, Y);

        // ---- FFN ----
        gemm_nt_tc<<<gF, blk>>>(Y, wf1 + (size_t)l * FF * DD, bf1 + (size_t)l * FF,
                                nullptr, Hb, MTOK, FF, DD, 1);
        gemm_nt_tc<<<gD, blk>>>(Hb, wf2 + (size_t)l * DD * FF, bf2 + vOff, Y, Y,
                                MTOK, DD, FF, 0);
        float* outl = out + (size_t)l * MTOK * DD;
        layernorm_row<<<MTOK, blk>>>(Y, g3 + vOff, be3 + vOff, outl);

        X = outl;   // next layer reads decoder state from the output slab
    }
    (void)in_sizes; (void)n_in; (void)out_size;
}